// round 16
// baseline (speedup 1.0000x reference)
#include <cuda_runtime.h>
#include <math.h>
#include <stdint.h>

typedef unsigned long long ull;

// Problem constants
#define BATCH 512
#define C 3
#define NIMG 128
#define LNUM 3
#define H_ELEMS (BATCH * C * NIMG * NIMG)   // 25165824
#define TILES 32                            // 4 x-tiles (32w) x 8 y-tiles (16h)
#define LN2F 0.69314718055994531f

// Padded ecb table: rows/cols shifted +2, wrap-replicated edges.
#define EP_ROWS 133
#define EP_COLS 134
#define EP_PLANE (EP_ROWS * EP_COLS)
#define EP_TOTAL (LNUM * C * EP_PLANE)      // 160398
#define ECB_BLKS 627                        // 627*256 >= EP_TOTAL

// ---------------- device scratch ----------------
__device__ __align__(16) float g_ecbP[EP_TOTAL * 2];
__device__ __align__(16) ull   g_Wpk[LNUM * 90];
__device__ __align__(16) float g_aux[LNUM * 12];
__device__ float g_cls_part[ECB_BLKS];
__device__ float g_kld_part[LNUM * 64];
__device__ float g_scratch[BATCH * TILES];

__constant__ ull   c_W[LNUM * 90];
__constant__ float c_aux[LNUM * 12];

// ---------------- packed f32x2 helpers ----------------
__device__ __forceinline__ ull pk(float lo, float hi) {
    ull r; asm("mov.b64 %0,{%1,%2};" : "=l"(r) : "f"(lo), "f"(hi)); return r;
}
__device__ __forceinline__ void upk(ull p, float& lo, float& hi) {
    asm("mov.b64 {%0,%1},%2;" : "=f"(lo), "=f"(hi) : "l"(p));
}
__device__ __forceinline__ ull f2fma(ull a, ull b, ull c) {
    ull d; asm("fma.rn.f32x2 %0,%1,%2,%3;" : "=l"(d) : "l"(a), "l"(b), "l"(c)); return d;
}
__device__ __forceinline__ ull mkmid(ull a, ull b) {
    float alo, ahi, blo, bhi;
    asm("mov.b64 {%0,%1},%2;" : "=f"(alo), "=f"(ahi) : "l"(a));
    asm("mov.b64 {%0,%1},%2;" : "=f"(blo), "=f"(bhi) : "l"(b));
    ull m; asm("mov.b64 %0,{%1,%2};" : "=l"(m) : "f"(ahi), "f"(blo));
    return m;
}

// =========================================================================
// P1: pre-wrapped padded {exp(cls), bias} table + partial cls sums
// =========================================================================
__global__ void prep_ecb(const float* __restrict__ cls, const float* __restrict__ cbias) {
    __shared__ float sred[256];
    int idx = blockIdx.x * 256 + threadIdx.x;
    if (idx < EP_TOTAL) {
        int col = idx % EP_COLS;
        int r2  = idx / EP_COLS;
        int row = r2 % EP_ROWS;
        int lo  = r2 / EP_ROWS;
        int gx = (col - 2) & 127;
        int gy = (row - 2) & 127;
        int src = (lo * 128 + gy) * 128 + gx;
        g_ecbP[2 * idx]     = expf(cls[src]);
        g_ecbP[2 * idx + 1] = cbias[src];
    }
    float v = 0.f;
    if (idx < LNUM * C * NIMG * NIMG) v = cls[idx];
    sred[threadIdx.x] = v;
    __syncthreads();
    for (int s = 128; s > 0; s >>= 1) {
        if (threadIdx.x < s) sred[threadIdx.x] += sred[threadIdx.x + s];
        __syncthreads();
    }
    if (threadIdx.x == 0) g_cls_part[blockIdx.x] = sred[0];
}

// =========================================================================
// P2: fold actnorm into conv weights; alpha tables
// =========================================================================
__global__ void prep_w(const float* __restrict__ K, const float* __restrict__ als,
                       const float* __restrict__ ab, const float* __restrict__ sla) {
    int t = threadIdx.x;
    for (int i = t; i < LNUM * 90; i += 256) {
        int l = i / 90, r = i % 90;
        int in = r / 30, r2 = r % 30;
        int o = r2 / 10, tap = r2 % 10;
        float val = 0.f;
        if (tap < 9) {
            float a = expf(als[l * 3 + in]);
            val = K[((l * 3 + o) * 3 + in) * 9 + tap] * a;
        }
        g_Wpk[i] = pk(val, val);
    }
    for (int i = t; i < LNUM * 12; i += 256) {
        int l = i / 12, j = i % 12;
        float val = 0.f;
        if (j < 3) {
            float s = 0.f;
            for (int in = 0; in < 3; in++) {
                float ks = 0.f;
                for (int tap = 0; tap < 9; tap++)
                    ks += K[((l * 3 + j) * 3 + in) * 9 + tap];
                s += ab[l * 3 + in] * ks;
            }
            val = s;
        } else if (j < 6) {
            val = expf(sla[l * 3 + (j - 3)]);
        } else if (j < 9) {
            val = LN2F / expf(sla[l * 3 + (j - 6)]);
        }
        g_aux[i] = val;
    }
}

// =========================================================================
// P3: spectral log|det|
// =========================================================================
__global__ void kld_kernel(const float* __restrict__ K) {
    __shared__ float2 tw[128];
    __shared__ float sK[LNUM * 81];
    __shared__ float sred[256];
    int tid = threadIdx.x;
    if (tid < 128) {
        double a = -2.0 * 3.14159265358979323846 * (double)tid / 128.0;
        double s, c; sincos(a, &s, &c);
        tw[tid] = make_float2((float)c, (float)s);
    }
    if (tid < LNUM * 81) sK[tid] = K[tid];
    __syncthreads();

    int point = blockIdx.x * 256 + tid;
    int u = point >> 7, v = point & 127;

    float res[LNUM];
    #pragma unroll
    for (int l = 0; l < LNUM; l++) {
        float er[9], ei[9];
        #pragma unroll
        for (int p = 0; p < 3; p++)
            #pragma unroll
            for (int q = 0; q < 3; q++) {
                int m = (u * p + v * q) & 127;
                float2 t = tw[m];
                er[p * 3 + q] = t.x; ei[p * 3 + q] = t.y;
            }
        float mr[3][3], mi[3][3];
        #pragma unroll
        for (int a = 0; a < 3; a++)
            #pragma unroll
            for (int b = 0; b < 3; b++) {
                float rr = 0.f, ri = 0.f;
                #pragma unroll
                for (int t = 0; t < 9; t++) {
                    float kk = sK[l * 81 + (a * 3 + b) * 9 + t];
                    rr += kk * er[t]; ri += kk * ei[t];
                }
                mr[a][b] = rr; mi[a][b] = ri;
            }
        float c0r = (mr[1][1]*mr[2][2] - mi[1][1]*mi[2][2]) - (mr[1][2]*mr[2][1] - mi[1][2]*mi[2][1]);
        float c0i = (mr[1][1]*mi[2][2] + mi[1][1]*mr[2][2]) - (mr[1][2]*mi[2][1] + mi[1][2]*mr[2][1]);
        float c1r = (mr[1][0]*mr[2][2] - mi[1][0]*mi[2][2]) - (mr[1][2]*mr[2][0] - mi[1][2]*mi[2][0]);
        float c1i = (mr[1][0]*mi[2][2] + mi[1][0]*mr[2][2]) - (mr[1][2]*mi[2][0] + mi[1][2]*mr[2][0]);
        float c2r = (mr[1][0]*mr[2][1] - mi[1][0]*mi[2][1]) - (mr[1][1]*mr[2][0] - mi[1][1]*mi[2][0]);
        float c2i = (mr[1][0]*mi[2][1] + mi[1][0]*mr[2][1]) - (mr[1][1]*mi[2][0] + mi[1][1]*mr[2][0]);
        float dr = (mr[0][0]*c0r - mi[0][0]*c0i) - (mr[0][1]*c1r - mi[0][1]*c1i) + (mr[0][2]*c2r - mi[0][2]*c2i);
        float di = (mr[0][0]*c0i + mi[0][0]*c0r) - (mr[0][1]*c1i + mi[0][1]*c1r) + (mr[0][2]*c2i + mi[0][2]*c2r);
        res[l] = 0.5f * logf(dr * dr + di * di);
    }

    for (int l = 0; l < LNUM; l++) {
        sred[tid] = res[l];
        __syncthreads();
        for (int s = 128; s > 0; s >>= 1) {
            if (tid < s) sred[tid] += sred[tid + s];
            __syncthreads();
        }
        if (tid == 0) g_kld_part[l * 64 + blockIdx.x] = sred[0];
        __syncthreads();
    }
}

// =========================================================================
// One 4-wide x 1-tall region. Input row = LDS.128 + LDS.64 (3 pairs + 2 mids).
// =========================================================================
template <int QW, bool LAST, int OFF, int LAYER>
__device__ __forceinline__ float do_region(int q,
                                           const float* __restrict__ sin_, int pin,
                                           float* __restrict__ sout, int pout,
                                           float* __restrict__ gout,
                                           const float2* __restrict__ ecbP,
                                           int ty0, int tx0) {
    int ry = q / QW, rx = q - ry * QW;
    int py = ry, px = rx * 4;

    ull acc[3][2];
    #pragma unroll
    for (int o = 0; o < 3; o++) {
        float B = c_aux[LAYER * 12 + o];
        acc[o][0] = pk(B, B);
        acc[o][1] = acc[o][0];
    }

    #pragma unroll
    for (int in = 0; in < 3; in++) {
        const float* bp = sin_ + in * pin + py * 40 + px;
        ull P01[3], P23[3], P45[3], M12[3], M34[3];
        #pragma unroll
        for (int r = 0; r < 3; r++) {
            ulonglong2 t = *(const ulonglong2*)(bp + r * 40);
            P01[r] = t.x; P23[r] = t.y;
            P45[r] = *(const ull*)(bp + r * 40 + 4);
            M12[r] = mkmid(P01[r], P23[r]);
            M34[r] = mkmid(P23[r], P45[r]);
        }
        #pragma unroll
        for (int o = 0; o < 3; o++) {
            #pragma unroll
            for (int r = 0; r < 3; r++) {
                ull w0 = c_W[LAYER * 90 + (in * 3 + o) * 10 + r * 3 + 0];
                ull w1 = c_W[LAYER * 90 + (in * 3 + o) * 10 + r * 3 + 1];
                ull w2 = c_W[LAYER * 90 + (in * 3 + o) * 10 + r * 3 + 2];
                acc[o][0] = f2fma(w0, P01[r], acc[o][0]);
                acc[o][0] = f2fma(w1, M12[r], acc[o][0]);
                acc[o][0] = f2fma(w2, P23[r], acc[o][0]);
                acc[o][1] = f2fma(w0, P23[r], acc[o][1]);
                acc[o][1] = f2fma(w1, M34[r], acc[o][1]);
                acc[o][1] = f2fma(w2, P45[r], acc[o][1]);
            }
        }
    }

    // ---- epilogue ----
    int xl0 = px - OFF, yloc = py - OFF;
    const float2* ep0 = ecbP + (ty0 + yloc + 2) * EP_COLS + (tx0 + xl0 + 2);

    float lg2sum = 0.f;
    #pragma unroll
    for (int o = 0; o < 3; o++) {
        float al   = c_aux[LAYER * 12 + 3 + o];
        float ial2 = c_aux[LAYER * 12 + 6 + o];
        float c0, c1, c2, c3;
        upk(acc[o][0], c0, c1);
        upk(acc[o][1], c2, c3);
        const float2* p = ep0 + o * EP_PLANE;
        float e0, b0, e1, b1, e2, b2, e3, b3;
        if ((OFF & 1) == 0) {
            // base float2-index even -> two aligned float4 loads
            float4 A4 = *(const float4*)p;
            float4 B4 = *(const float4*)(p + 2);
            e0 = A4.x; b0 = A4.y; e1 = A4.z; b1 = A4.w;
            e2 = B4.x; b2 = B4.y; e3 = B4.z; b3 = B4.w;
        } else {
            float2 t0 = p[0], t1 = p[1], t2 = p[2], t3 = p[3];
            e0 = t0.x; b0 = t0.y; e1 = t1.x; b1 = t1.y;
            e2 = t2.x; b2 = t2.y; e3 = t3.x; b3 = t3.y;
        }
        float u0 = fmaf(e0, c0, b0);
        float u1 = fmaf(e1, c1, b1);
        float u2 = fmaf(e2, c2, b2);
        float u3 = fmaf(e3, c3, b3);
        float g0 = __log2f(fmaf(al, fabsf(u0), 1.0f));
        float g1 = __log2f(fmaf(al, fabsf(u1), 1.0f));
        float g2 = __log2f(fmaf(al, fabsf(u2), 1.0f));
        float g3 = __log2f(fmaf(al, fabsf(u3), 1.0f));
        float h0 = copysignf(ial2 * g0, u0);
        float h1 = copysignf(ial2 * g1, u1);
        float h2 = copysignf(ial2 * g2, u2);
        float h3 = copysignf(ial2 * g3, u3);
        bool yok = LAST || (unsigned)yloc < 16u;
        if (yok && (LAST || (unsigned)(xl0 + 0) < 32u)) lg2sum += g0;
        if (yok && (LAST || (unsigned)(xl0 + 1) < 32u)) lg2sum += g1;
        if (yok && (LAST || (unsigned)(xl0 + 2) < 32u)) lg2sum += g2;
        if (yok && (LAST || (unsigned)(xl0 + 3) < 32u)) lg2sum += g3;
        if (!LAST) {
            ulonglong2 st;
            st.x = pk(h0, h1);
            st.y = pk(h2, h3);
            *(ulonglong2*)&sout[o * pout + py * 40 + px] = st;
        } else {
            // OFF==0: gy = ty0+py never wraps
            *(float4*)(gout + ((size_t)o * NIMG + (ty0 + py)) * NIMG + (tx0 + px)) =
                make_float4(h0, h1, h2, h3);
        }
    }
    return lg2sum;
}

// =========================================================================
// One stage (128 threads). Overflow regions rotated per stage.
// =========================================================================
template <int QW, int ROWS, bool LAST, int OFF, int LAYER, bool HIGH_OVF>
__device__ __forceinline__ float stage_p(const float* __restrict__ sin_, int pin,
                                         float* __restrict__ sout, int pout,
                                         float* __restrict__ gout,
                                         int ty0, int tx0, int tid) {
    const float2* __restrict__ ecbP =
        (const float2*)g_ecbP + (size_t)LAYER * (C * EP_PLANE);
    constexpr int NQ = QW * ROWS;   // 180 / 162 / 128

    float s = do_region<QW, LAST, OFF, LAYER>(tid, sin_, pin, sout, pout, gout, ecbP, ty0, tx0);
    if constexpr (NQ > 128) {
        constexpr int V = NQ - 128;
        if constexpr (HIGH_OVF) {
            if (tid >= 128 - V)
                s += do_region<QW, LAST, OFF, LAYER>(tid + V, sin_, pin, sout, pout, gout, ecbP, ty0, tx0);
        } else {
            if (tid < V)
                s += do_region<QW, LAST, OFF, LAYER>(tid + 128, sin_, pin, sout, pout, gout, ecbP, ty0, tx0);
        }
    }
    return s;
}

__global__ void __launch_bounds__(128, 6) flow_main(const float* __restrict__ x,
                                                    float* __restrict__ out) {
    const int tid = threadIdx.x;
    const int b = blockIdx.x;        // batch-major
    const int tile = blockIdx.y;     // 0..31 : 4 x-tiles * 8 y-tiles
    const int tx0 = (tile & 3) * 32;
    const int ty0 = (tile >> 2) * 16;

    __shared__ __align__(16) float sA[3 * 22 * 40];
    __shared__ __align__(16) float sB[3 * 20 * 40];
    __shared__ float sred[128];

    // Vectorized loader: float4 LDG wrapped at float4-column granularity,
    // predicated scalar STS (local col 0 <-> gx tx0-3; 38 cols, 22 rows).
    const float4* __restrict__ xb4 =
        (const float4*)(x + (size_t)b * (C * NIMG * NIMG));
    const int gx4base = tx0 >> 2;
    for (int u = tid; u < 66 * 10; u += 128) {       // 66 rows (3ch x 22), 10 float4
        int row = u / 10, k = u - row * 10;
        int c = row / 22, r = row - c * 22;
        int gx4 = (gx4base - 1 + k) & 31;
        int gy  = (ty0 + r - 3) & 127;
        float4 v = xb4[((c << 7) + gy) * 32 + gx4];
        float* dst = sA + c * (22 * 40) + r * 40;
        int Lb = k * 4 - 1;
        if ((unsigned)(Lb + 0) < 38u) dst[Lb + 0] = v.x;
        if ((unsigned)(Lb + 1) < 38u) dst[Lb + 1] = v.y;
        if ((unsigned)(Lb + 2) < 38u) dst[Lb + 2] = v.z;
        if ((unsigned)(Lb + 3) < 38u) dst[Lb + 3] = v.w;
    }
    __syncthreads();

    float lg2acc = 0.f;
    // stage0: 20 rows x 9 regions (36 wide), overflow 52 -> high tids
    lg2acc += stage_p<9, 20, false, 2, 0, true >(sA, 22 * 40, sB, 20 * 40, nullptr, ty0, tx0, tid);
    __syncthreads();
    // stage1: 18 rows x 9 regions (36 wide; cols 34-35 garbage, excluded+unread),
    //         overflow 34 -> low tids
    lg2acc += stage_p<9, 18, false, 1, 1, false>(sB, 20 * 40, sA, 18 * 40, nullptr, ty0, tx0, tid);
    __syncthreads();
    // stage2: 16 rows x 8 regions (32 wide), exact fit
    lg2acc += stage_p<8, 16, true, 0, 2, false>(sA, 18 * 40, nullptr, 0,
                                                out + (size_t)b * (C * NIMG * NIMG), ty0, tx0, tid);

    sred[tid] = lg2acc;
    __syncthreads();
    for (int s = 64; s > 0; s >>= 1) {
        if (tid < s) sred[tid] += sred[tid + s];
        __syncthreads();
    }
    if (tid == 0) g_scratch[b * TILES + tile] = -LN2F * sred[0];
}

// =========================================================================
// F: per-batch logdet = scalar part + 32 tile partials (deterministic)
// =========================================================================
__global__ void final_ld(const float* __restrict__ als, float* __restrict__ out) {
    __shared__ float sred[256];
    int tid = threadIdx.x;
    float loc = 0.f;
    for (int i = tid; i < ECB_BLKS; i += 256) loc += g_cls_part[i];
    for (int i = tid; i < LNUM * 64; i += 256) loc += g_kld_part[i];
    sred[tid] = loc;
    __syncthreads();
    for (int s = 128; s > 0; s >>= 1) {
        if (tid < s) sred[tid] += sred[tid + s];
        __syncthreads();
    }
    if (tid == 0) {
        float s2 = 0.f;
        for (int i = 0; i < 9; i++) s2 += als[i];
        sred[0] = sred[0] + 16384.0f * s2;
    }
    __syncthreads();
    float scal = sred[0];
    int b = blockIdx.x * 256 + tid;
    if (b < BATCH) {
        float s = scal;
        #pragma unroll
        for (int t = 0; t < TILES; t++) s += g_scratch[b * TILES + t];
        out[H_ELEMS + b] = s;
    }
}

// =========================================================================
extern "C" void kernel_launch(void* const* d_in, const int* in_sizes, int n_in,
                              void* d_out, int out_size) {
    const float* x     = (const float*)d_in[0];
    const float* ab    = (const float*)d_in[1];
    const float* als   = (const float*)d_in[2];
    const float* K     = (const float*)d_in[3];
    const float* cbias = (const float*)d_in[4];
    const float* cls   = (const float*)d_in[5];
    const float* sla   = (const float*)d_in[6];
    float* out = (float*)d_out;

    prep_ecb<<<ECB_BLKS, 256>>>(cls, cbias);
    prep_w<<<1, 256>>>(K, als, ab, sla);
    kld_kernel<<<64, 256>>>(K);

    // Device->constant-bank copies (graph-capturable D2D memcpy nodes).
    void* wsrc = nullptr;
    cudaGetSymbolAddress(&wsrc, g_Wpk);
    cudaMemcpyToSymbolAsync(c_W, wsrc, sizeof(ull) * LNUM * 90, 0,
                            cudaMemcpyDeviceToDevice, 0);
    void* asrc = nullptr;
    cudaGetSymbolAddress(&asrc, g_aux);
    cudaMemcpyToSymbolAsync(c_aux, asrc, sizeof(float) * LNUM * 12, 0,
                            cudaMemcpyDeviceToDevice, 0);

    flow_main<<<dim3(BATCH, TILES), 128>>>(x, out);   // 4th kernel (ncu target)
    final_ld<<<2, 256>>>(als, out);
}

// round 17
// speedup vs baseline: 1.1146x; 1.1146x over previous
#include <cuda_runtime.h>
#include <math.h>
#include <stdint.h>

typedef unsigned long long ull;

// Problem constants
#define BATCH 512
#define C 3
#define NIMG 128
#define LNUM 3
#define H_ELEMS (BATCH * C * NIMG * NIMG)   // 25165824
#define TILES 16                            // 4x4 tiles of 32x32
#define LN2F 0.69314718055994531f

// Padded ecb table: rows/cols shifted +2, wrap-replicated edges.
#define EP_ROWS 133
#define EP_COLS 134
#define EP_PLANE (EP_ROWS * EP_COLS)
#define EP_TOTAL (LNUM * C * EP_PLANE)      // 160398
#define ECB_BLKS 627                        // 627*256 >= EP_TOTAL

// ---------------- device scratch ----------------
__device__ __align__(16) float g_ecbP[EP_TOTAL * 2];
__device__ __align__(16) ull   g_Wpk[LNUM * 90];
__device__ __align__(16) float g_aux[LNUM * 12];
__device__ float g_cls_part[ECB_BLKS];
__device__ float g_kld_part[LNUM * 64];
__device__ float g_scratch[BATCH * TILES];

__constant__ ull   c_W[LNUM * 90];
__constant__ float c_aux[LNUM * 12];

// ---------------- packed f32x2 helpers ----------------
__device__ __forceinline__ ull pk(float lo, float hi) {
    ull r; asm("mov.b64 %0,{%1,%2};" : "=l"(r) : "f"(lo), "f"(hi)); return r;
}
__device__ __forceinline__ void upk(ull p, float& lo, float& hi) {
    asm("mov.b64 {%0,%1},%2;" : "=f"(lo), "=f"(hi) : "l"(p));
}
__device__ __forceinline__ ull f2fma(ull a, ull b, ull c) {
    ull d; asm("fma.rn.f32x2 %0,%1,%2,%3;" : "=l"(d) : "l"(a), "l"(b), "l"(c)); return d;
}
__device__ __forceinline__ ull mkmid(ull a, ull b) {
    float alo, ahi, blo, bhi;
    asm("mov.b64 {%0,%1},%2;" : "=f"(alo), "=f"(ahi) : "l"(a));
    asm("mov.b64 {%0,%1},%2;" : "=f"(blo), "=f"(bhi) : "l"(b));
    ull m; asm("mov.b64 %0,{%1,%2};" : "=l"(m) : "f"(ahi), "f"(blo));
    return m;
}

// =========================================================================
// P1: pre-wrapped padded {exp(cls), bias} table + partial cls sums
// =========================================================================
__global__ void prep_ecb(const float* __restrict__ cls, const float* __restrict__ cbias) {
    __shared__ float sred[256];
    int idx = blockIdx.x * 256 + threadIdx.x;
    if (idx < EP_TOTAL) {
        int col = idx % EP_COLS;
        int r2  = idx / EP_COLS;
        int row = r2 % EP_ROWS;
        int lo  = r2 / EP_ROWS;
        int gx = (col - 2) & 127;
        int gy = (row - 2) & 127;
        int src = (lo * 128 + gy) * 128 + gx;
        g_ecbP[2 * idx]     = expf(cls[src]);
        g_ecbP[2 * idx + 1] = cbias[src];
    }
    float v = 0.f;
    if (idx < LNUM * C * NIMG * NIMG) v = cls[idx];
    sred[threadIdx.x] = v;
    __syncthreads();
    for (int s = 128; s > 0; s >>= 1) {
        if (threadIdx.x < s) sred[threadIdx.x] += sred[threadIdx.x + s];
        __syncthreads();
    }
    if (threadIdx.x == 0) g_cls_part[blockIdx.x] = sred[0];
}

// =========================================================================
// P2: fold actnorm into conv weights; alpha tables
// =========================================================================
__global__ void prep_w(const float* __restrict__ K, const float* __restrict__ als,
                       const float* __restrict__ ab, const float* __restrict__ sla) {
    int t = threadIdx.x;
    for (int i = t; i < LNUM * 90; i += 256) {
        int l = i / 90, r = i % 90;
        int in = r / 30, r2 = r % 30;
        int o = r2 / 10, tap = r2 % 10;
        float val = 0.f;
        if (tap < 9) {
            float a = expf(als[l * 3 + in]);
            val = K[((l * 3 + o) * 3 + in) * 9 + tap] * a;
        }
        g_Wpk[i] = pk(val, val);
    }
    for (int i = t; i < LNUM * 12; i += 256) {
        int l = i / 12, j = i % 12;
        float val = 0.f;
        if (j < 3) {
            float s = 0.f;
            for (int in = 0; in < 3; in++) {
                float ks = 0.f;
                for (int tap = 0; tap < 9; tap++)
                    ks += K[((l * 3 + j) * 3 + in) * 9 + tap];
                s += ab[l * 3 + in] * ks;
            }
            val = s;
        } else if (j < 6) {
            val = expf(sla[l * 3 + (j - 3)]);
        } else if (j < 9) {
            val = LN2F / expf(sla[l * 3 + (j - 6)]);
        }
        g_aux[i] = val;
    }
}

// =========================================================================
// P3: spectral log|det|
// =========================================================================
__global__ void kld_kernel(const float* __restrict__ K) {
    __shared__ float2 tw[128];
    __shared__ float sK[LNUM * 81];
    __shared__ float sred[256];
    int tid = threadIdx.x;
    if (tid < 128) {
        double a = -2.0 * 3.14159265358979323846 * (double)tid / 128.0;
        double s, c; sincos(a, &s, &c);
        tw[tid] = make_float2((float)c, (float)s);
    }
    if (tid < LNUM * 81) sK[tid] = K[tid];
    __syncthreads();

    int point = blockIdx.x * 256 + tid;
    int u = point >> 7, v = point & 127;

    float res[LNUM];
    #pragma unroll
    for (int l = 0; l < LNUM; l++) {
        float er[9], ei[9];
        #pragma unroll
        for (int p = 0; p < 3; p++)
            #pragma unroll
            for (int q = 0; q < 3; q++) {
                int m = (u * p + v * q) & 127;
                float2 t = tw[m];
                er[p * 3 + q] = t.x; ei[p * 3 + q] = t.y;
            }
        float mr[3][3], mi[3][3];
        #pragma unroll
        for (int a = 0; a < 3; a++)
            #pragma unroll
            for (int b = 0; b < 3; b++) {
                float rr = 0.f, ri = 0.f;
                #pragma unroll
                for (int t = 0; t < 9; t++) {
                    float kk = sK[l * 81 + (a * 3 + b) * 9 + t];
                    rr += kk * er[t]; ri += kk * ei[t];
                }
                mr[a][b] = rr; mi[a][b] = ri;
            }
        float c0r = (mr[1][1]*mr[2][2] - mi[1][1]*mi[2][2]) - (mr[1][2]*mr[2][1] - mi[1][2]*mi[2][1]);
        float c0i = (mr[1][1]*mi[2][2] + mi[1][1]*mr[2][2]) - (mr[1][2]*mi[2][1] + mi[1][2]*mr[2][1]);
        float c1r = (mr[1][0]*mr[2][2] - mi[1][0]*mi[2][2]) - (mr[1][2]*mr[2][0] - mi[1][2]*mi[2][0]);
        float c1i = (mr[1][0]*mi[2][2] + mi[1][0]*mr[2][2]) - (mr[1][2]*mi[2][0] + mi[1][2]*mr[2][0]);
        float c2r = (mr[1][0]*mr[2][1] - mi[1][0]*mi[2][1]) - (mr[1][1]*mr[2][0] - mi[1][1]*mi[2][0]);
        float c2i = (mr[1][0]*mi[2][1] + mi[1][0]*mr[2][1]) - (mr[1][1]*mi[2][0] + mi[1][1]*mr[2][0]);
        float dr = (mr[0][0]*c0r - mi[0][0]*c0i) - (mr[0][1]*c1r - mi[0][1]*c1i) + (mr[0][2]*c2r - mi[0][2]*c2i);
        float di = (mr[0][0]*c0i + mi[0][0]*c0r) - (mr[0][1]*c1i + mi[0][1]*c1r) + (mr[0][2]*c2i + mi[0][2]*c2r);
        res[l] = 0.5f * logf(dr * dr + di * di);
    }

    for (int l = 0; l < LNUM; l++) {
        sred[tid] = res[l];
        __syncthreads();
        for (int s = 128; s > 0; s >>= 1) {
            if (tid < s) sred[tid] += sred[tid + s];
            __syncthreads();
        }
        if (tid == 0) g_kld_part[l * 64 + blockIdx.x] = sred[0];
        __syncthreads();
    }
}

// =========================================================================
// One 2-wide x 4-tall region, row-streamed. Out rows py..py+3 (cols px,px+1)
// read input rows py..py+5, cols px..px+3 (A=px,px+1; Bv=px+2,px+3; M=mid).
// =========================================================================
template <int QW, bool LAST, int OFF, int LAYER>
__device__ __forceinline__ float do_region(int q,
                                           const float* __restrict__ sin_, int pin,
                                           float* __restrict__ sout, int pout,
                                           float* __restrict__ gout,
                                           const float2* __restrict__ ecbP,
                                           int ty0, int tx0) {
    int ry = q / QW, rx = q - ry * QW;
    int py = ry * 4, px = rx * 2;

    ull acc[4][3];
    #pragma unroll
    for (int o = 0; o < 3; o++) {
        float B = c_aux[LAYER * 12 + o];
        ull Bp = pk(B, B);
        acc[0][o] = Bp; acc[1][o] = Bp; acc[2][o] = Bp; acc[3][o] = Bp;
    }

    #pragma unroll
    for (int in = 0; in < 3; in++) {
        const float* bp = sin_ + in * pin + py * 40 + px;
        #pragma unroll
        for (int rr = 0; rr < 6; rr++) {
            ull A  = *(const ull*)(bp + rr * 40);
            ull Bv = *(const ull*)(bp + rr * 40 + 2);
            ull M  = mkmid(A, Bv);
            #pragma unroll
            for (int o = 0; o < 3; o++) {
                #pragma unroll
                for (int d = 0; d < 3; d++) {
                    constexpr_helper: ;
                    int r_out = rr - d;
                    if (r_out >= 0 && r_out < 4) {
                        ull w0 = c_W[LAYER * 90 + (in * 3 + o) * 10 + d * 3 + 0];
                        ull w1 = c_W[LAYER * 90 + (in * 3 + o) * 10 + d * 3 + 1];
                        ull w2 = c_W[LAYER * 90 + (in * 3 + o) * 10 + d * 3 + 2];
                        acc[r_out][o] = f2fma(w0, A,  acc[r_out][o]);
                        acc[r_out][o] = f2fma(w1, M,  acc[r_out][o]);
                        acc[r_out][o] = f2fma(w2, Bv, acc[r_out][o]);
                    }
                }
            }
        }
    }

    // ---- epilogue ----
    int xl0 = px - OFF, yl0 = py - OFF;
    const float2* ep0 = ecbP + (ty0 + yl0 + 2) * EP_COLS + (tx0 + xl0 + 2);

    float lg2sum = 0.f;
    #pragma unroll
    for (int R = 0; R < 4; R++) {
        int yloc = yl0 + R;
        #pragma unroll
        for (int o = 0; o < 3; o++) {
            float al   = c_aux[LAYER * 12 + 3 + o];
            float ial2 = c_aux[LAYER * 12 + 6 + o];
            float c0, c1; upk(acc[R][o], c0, c1);
            const float2* p = ep0 + o * EP_PLANE + R * EP_COLS;
            float e0, b0, e1, b1;
            if ((OFF & 1) == 0) {
                float4 E = *(const float4*)p;   // base float2-index even -> aligned
                e0 = E.x; b0 = E.y; e1 = E.z; b1 = E.w;
            } else {
                float2 t0 = p[0], t1 = p[1];
                e0 = t0.x; b0 = t0.y; e1 = t1.x; b1 = t1.y;
            }
            float u0 = fmaf(e0, c0, b0);
            float u1 = fmaf(e1, c1, b1);
            float g0 = __log2f(fmaf(al, fabsf(u0), 1.0f));
            float g1 = __log2f(fmaf(al, fabsf(u1), 1.0f));
            float h0 = copysignf(ial2 * g0, u0);
            float h1 = copysignf(ial2 * g1, u1);
            bool yok = LAST || (unsigned)yloc < 32u;
            if (yok && (LAST || (unsigned)(xl0 + 0) < 32u)) lg2sum += g0;
            if (yok && (LAST || (unsigned)(xl0 + 1) < 32u)) lg2sum += g1;
            if (!LAST) {
                *(ull*)&sout[o * pout + (py + R) * 40 + px] = pk(h0, h1);
            } else {
                // OFF==0: gy = ty0+py+R never wraps
                *(float2*)(gout + ((size_t)o * NIMG + (ty0 + py + R)) * NIMG + (tx0 + px)) =
                    make_float2(h0, h1);
            }
        }
    }
    return lg2sum;
}

// =========================================================================
// One stage (128 threads). Overflow regions rotated per stage.
// =========================================================================
template <int QW, int RG, bool LAST, int OFF, int LAYER, bool HIGH_OVF>
__device__ __forceinline__ float stage_p(const float* __restrict__ sin_, int pin,
                                         float* __restrict__ sout, int pout,
                                         float* __restrict__ gout,
                                         int ty0, int tx0, int tid) {
    const float2* __restrict__ ecbP =
        (const float2*)g_ecbP + (size_t)LAYER * (C * EP_PLANE);
    constexpr int NQ = QW * RG;   // 162 / 153 / 128

    float s = do_region<QW, LAST, OFF, LAYER>(tid, sin_, pin, sout, pout, gout, ecbP, ty0, tx0);
    if constexpr (NQ > 128) {
        constexpr int V = NQ - 128;
        if constexpr (HIGH_OVF) {
            if (tid >= 128 - V)
                s += do_region<QW, LAST, OFF, LAYER>(tid + V, sin_, pin, sout, pout, gout, ecbP, ty0, tx0);
        } else {
            if (tid < V)
                s += do_region<QW, LAST, OFF, LAYER>(tid + 128, sin_, pin, sout, pout, gout, ecbP, ty0, tx0);
        }
    }
    return s;
}

__global__ void __launch_bounds__(128, 6) flow_main(const float* __restrict__ x,
                                                    float* __restrict__ out) {
    const int tid = threadIdx.x;
    const int b = blockIdx.x;        // batch-major
    const int tile = blockIdx.y;     // 0..15 : 4x4 tiles of 32x32
    const int tx0 = (tile & 3) * 32;
    const int ty0 = (tile >> 2) * 32;

    __shared__ __align__(16) float sA[3 * 38 * 40];   // input / stage1 out
    __shared__ __align__(16) float sB[3 * 38 * 40];   // stage0 out (rows 36,37 zeroed)
    __shared__ float sred[128];

    // Vectorized loader: float4 LDG wrapped at float4-column granularity,
    // predicated scalar STS (local col 0 <-> gx tx0-3; 38 cols, 38 rows).
    const float4* __restrict__ xb4 =
        (const float4*)(x + (size_t)b * (C * NIMG * NIMG));
    const int gx4base = tx0 >> 2;
    for (int u = tid; u < 114 * 10; u += 128) {      // 114 rows (3ch x 38), 10 float4
        int row = u / 10, k = u - row * 10;
        int c = row / 38, r = row - c * 38;
        int gx4 = (gx4base - 1 + k) & 31;
        int gy  = (ty0 + r - 3) & 127;
        float4 v = xb4[((c << 7) + gy) * 32 + gx4];
        float* dst = sA + c * (38 * 40) + r * 40;
        int Lb = k * 4 - 1;
        if ((unsigned)(Lb + 0) < 38u) dst[Lb + 0] = v.x;
        if ((unsigned)(Lb + 1) < 38u) dst[Lb + 1] = v.y;
        if ((unsigned)(Lb + 2) < 38u) dst[Lb + 2] = v.z;
        if ((unsigned)(Lb + 3) < 38u) dst[Lb + 3] = v.w;
    }
    // Zero sB rows 36,37 (read by stage1 overcompute rows; values excluded)
    for (int i = tid; i < 240; i += 128) {
        int c = i / 80, rem = i - c * 80;
        sB[c * (38 * 40) + (36 + rem / 40) * 40 + (rem % 40)] = 0.f;
    }
    __syncthreads();

    float lg2acc = 0.f;
    // stage0: 18 strips x 9 groups (36 rows x 36 cols), overflow 34 -> high tids
    lg2acc += stage_p<18, 9, false, 2, 0, true >(sA, 38 * 40, sB, 38 * 40, nullptr, ty0, tx0, tid);
    __syncthreads();
    // stage1: 17 strips x 9 groups (36 rows computed, rows 34-35 garbage/excluded;
    //         34 cols), overflow 25 -> low tids
    lg2acc += stage_p<17, 9, false, 1, 1, false>(sB, 38 * 40, sA, 38 * 40, nullptr, ty0, tx0, tid);
    __syncthreads();
    // stage2: 16 strips x 8 groups (32 x 32), exact fit
    lg2acc += stage_p<16, 8, true, 0, 2, false>(sA, 38 * 40, nullptr, 0,
                                                out + (size_t)b * (C * NIMG * NIMG), ty0, tx0, tid);

    sred[tid] = lg2acc;
    __syncthreads();
    for (int s = 64; s > 0; s >>= 1) {
        if (tid < s) sred[tid] += sred[tid + s];
        __syncthreads();
    }
    if (tid == 0) g_scratch[b * TILES + tile] = -LN2F * sred[0];
}

// =========================================================================
// F: per-batch logdet = scalar part + 16 tile partials (deterministic)
// =========================================================================
__global__ void final_ld(const float* __restrict__ als, float* __restrict__ out) {
    __shared__ float sred[256];
    int tid = threadIdx.x;
    float loc = 0.f;
    for (int i = tid; i < ECB_BLKS; i += 256) loc += g_cls_part[i];
    for (int i = tid; i < LNUM * 64; i += 256) loc += g_kld_part[i];
    sred[tid] = loc;
    __syncthreads();
    for (int s = 128; s > 0; s >>= 1) {
        if (tid < s) sred[tid] += sred[tid + s];
        __syncthreads();
    }
    if (tid == 0) {
        float s2 = 0.f;
        for (int i = 0; i < 9; i++) s2 += als[i];
        sred[0] = sred[0] + 16384.0f * s2;
    }
    __syncthreads();
    float scal = sred[0];
    int b = blockIdx.x * 256 + tid;
    if (b < BATCH) {
        float s = scal;
        #pragma unroll
        for (int t = 0; t < TILES; t++) s += g_scratch[b * TILES + t];
        out[H_ELEMS + b] = s;
    }
}

// =========================================================================
extern "C" void kernel_launch(void* const* d_in, const int* in_sizes, int n_in,
                              void* d_out, int out_size) {
    const float* x     = (const float*)d_in[0];
    const float* ab    = (const float*)d_in[1];
    const float* als   = (const float*)d_in[2];
    const float* K     = (const float*)d_in[3];
    const float* cbias = (const float*)d_in[4];
    const float* cls   = (const float*)d_in[5];
    const float* sla   = (const float*)d_in[6];
    float* out = (float*)d_out;

    prep_ecb<<<ECB_BLKS, 256>>>(cls, cbias);
    prep_w<<<1, 256>>>(K, als, ab, sla);
    kld_kernel<<<64, 256>>>(K);

    // Device->constant-bank copies (graph-capturable D2D memcpy nodes).
    void* wsrc = nullptr;
    cudaGetSymbolAddress(&wsrc, g_Wpk);
    cudaMemcpyToSymbolAsync(c_W, wsrc, sizeof(ull) * LNUM * 90, 0,
                            cudaMemcpyDeviceToDevice, 0);
    void* asrc = nullptr;
    cudaGetSymbolAddress(&asrc, g_aux);
    cudaMemcpyToSymbolAsync(c_aux, asrc, sizeof(float) * LNUM * 12, 0,
                            cudaMemcpyDeviceToDevice, 0);

    flow_main<<<dim3(BATCH, TILES), 128>>>(x, out);   // 4th kernel (ncu target)
    final_ld<<<2, 256>>>(als, out);
}